// round 14
// baseline (speedup 1.0000x reference)
#include <cuda_runtime.h>

#define TT 1024

// Inter-layer activations (device globals: allowed scratch)
__device__ float g_h1[256u * 1024u * 32u];        // layer1 output  (33.5 MB)
__device__ float g_h2[256u * 1024u * 64u];        // layer2 output  (67 MB)
__device__ float g_xg3[(size_t)256 * 1024 * 512]; // layer3 input proj + bias (512 MB)

typedef unsigned long long u64;

// ---------------- packed f32x2 helpers ----------------
__device__ __forceinline__ u64 ffma2(u64 a, u64 b, u64 c) {
    u64 d;
    asm("fma.rn.f32x2 %0, %1, %2, %3;" : "=l"(d) : "l"(a), "l"(b), "l"(c));
    return d;
}
__device__ __forceinline__ u64 pack2(float x, float y) {
    u64 r;
    asm("mov.b64 %0, {%1, %2};" : "=l"(r) : "f"(x), "f"(y));
    return r;
}
__device__ __forceinline__ float hsum2(u64 v) {
    float x, y;
    asm("mov.b64 {%0, %1}, %2;" : "=f"(x), "=f"(y) : "l"(v));
    return x + y;
}
__device__ __forceinline__ void unpack2(u64 v, float& x, float& y) {
    asm("mov.b64 {%0, %1}, %2;" : "=f"(x), "=f"(y) : "l"(v));
}
// ---------------- activations (proven: rel_err 4e-7) --------
__device__ __forceinline__ float rcpa(float x) {
    float r; asm("rcp.approx.f32 %0, %1;" : "=f"(r) : "f"(x)); return r;
}
__device__ __forceinline__ float sigf(float x)   { return rcpa(1.f + __expf(-x)); }
__device__ __forceinline__ float tanhf_(float x) { return 1.f - 2.f * rcpa(__expf(2.f * x) + 1.f); }

// ---------------- cluster helpers (R4/R6-proven) ----------------
__device__ __forceinline__ unsigned smem_u32(const void* p) {
    return (unsigned)__cvta_generic_to_shared(p);
}
__device__ __forceinline__ unsigned mapa_u32(unsigned a, unsigned r) {
    unsigned o; asm("mapa.shared::cluster.u32 %0, %1, %2;" : "=r"(o) : "r"(a), "r"(r)); return o;
}
__device__ __forceinline__ void st_cluster(unsigned a, float v) {
    asm volatile("st.shared::cluster.f32 [%0], %1;" :: "r"(a), "f"(v) : "memory");
}
__device__ __forceinline__ void cluster_sync_() {
    asm volatile("barrier.cluster.arrive.aligned;" ::: "memory");
    asm volatile("barrier.cluster.wait.aligned;"   ::: "memory");
}
__device__ __forceinline__ unsigned ctarank_() {
    unsigned r; asm("mov.u32 %0, %%cluster_ctarank;" : "=r"(r)); return r;
}

// =======================================================================
// Layer 1 v2: in=1, hid=32.  One WARP per batch; zero barriers.
// 4 accumulator chains. 128 blocks x 64 threads. (passed R12)
// =======================================================================
__global__ void __launch_bounds__(64, 1) lstm1_kernel(
    const float* __restrict__ x,    const float* __restrict__ w_ih,
    const float* __restrict__ w_hh, const float* __restrict__ b_ih,
    const float* __restrict__ b_hh)
{
    const int tid = threadIdx.x;
    const int j   = tid & 31;
    const int b   = blockIdx.x * 2 + (tid >> 5);

    u64 wif[32], wgo[32];
    #pragma unroll
    for (int k = 0; k < 32; k++) {
        wif[k] = pack2(w_hh[(0  + j) * 32 + k], w_hh[(32 + j) * 32 + k]);
        wgo[k] = pack2(w_hh[(64 + j) * 32 + k], w_hh[(96 + j) * 32 + k]);
    }
    const u64 bif  = pack2(b_ih[j]      + b_hh[j],      b_ih[32 + j] + b_hh[32 + j]);
    const u64 bgo  = pack2(b_ih[64 + j] + b_hh[64 + j], b_ih[96 + j] + b_hh[96 + j]);
    const u64 wiif = pack2(w_ih[j],      w_ih[32 + j]);
    const u64 wigo = pack2(w_ih[64 + j], w_ih[96 + j]);

    const float* __restrict__ xp = x + (size_t)b * TT;
    float* __restrict__ op = g_h1 + (size_t)b * TT * 32 + j;
    float h = 0.f, c = 0.f;
    float xt = xp[0];

    for (int t = 0; t < TT; t++) {
        float xn = (t + 1 < TT) ? xp[t + 1] : 0.f;
        u64 xtp = pack2(xt, xt);
        u64 aif0 = ffma2(wiif, xtp, bif);
        u64 ago0 = ffma2(wigo, xtp, bgo);
        u64 aif1 = pack2(0.f, 0.f), ago1 = aif1;
        #pragma unroll
        for (int k = 0; k < 16; k++) {
            float hk  = __shfl_sync(0xffffffffu, h, k);
            float hk2 = __shfl_sync(0xffffffffu, h, k + 16);
            u64 hp  = pack2(hk,  hk);
            u64 hp2 = pack2(hk2, hk2);
            aif0 = ffma2(wif[k],      hp,  aif0);
            ago0 = ffma2(wgo[k],      hp,  ago0);
            aif1 = ffma2(wif[k + 16], hp2, aif1);
            ago1 = ffma2(wgo[k + 16], hp2, ago1);
        }
        float i0, f0, i1, f1, g0, o0, g1, o1;
        unpack2(aif0, i0, f0); unpack2(aif1, i1, f1);
        unpack2(ago0, g0, o0); unpack2(ago1, g1, o1);
        float gi = i0 + i1, gf = f0 + f1, gg = g0 + g1, go = o0 + o1;
        c = sigf(gf) * c + sigf(gi) * tanhf_(gg);
        h = sigf(go) * tanhf_(c);
        op[(size_t)t * 32] = h;
        xt = xn;
    }
}

// =======================================================================
// Layer 2: in=32, hid=64.  ONE batch per CTA, 256 CTAs x 256 threads.
// (R12 proven version: updater tid<64)
// =======================================================================
__global__ void __launch_bounds__(256, 2) lstm2_kernel(
    const float* __restrict__ w_ih, const float* __restrict__ w_hh,
    const float* __restrict__ b_ih, const float* __restrict__ b_hh)
{
    __shared__ __align__(16) float h_sm[2][64];
    __shared__ __align__(16) float x_sm[2][32];
    __shared__ float g_sm[256];
    const int tid = threadIdx.x;
    const int b   = blockIdx.x;

    u64 wh[32], wi[16];
    {
        const ulonglong2* wr = (const ulonglong2*)(w_hh + (size_t)tid * 64);
        #pragma unroll
        for (int q = 0; q < 16; q++) { ulonglong2 v = wr[q]; wh[2*q] = v.x; wh[2*q+1] = v.y; }
        const ulonglong2* wr2 = (const ulonglong2*)(w_ih + (size_t)tid * 32);
        #pragma unroll
        for (int q = 0; q < 8; q++)  { ulonglong2 v = wr2[q]; wi[2*q] = v.x; wi[2*q+1] = v.y; }
    }
    const float bs = b_ih[tid] + b_hh[tid];
    const float* __restrict__ xin = g_h1 + (size_t)b * TT * 32;
    float* __restrict__ op = g_h2 + (size_t)b * TT * 64;

    if (tid < 64) h_sm[0][tid] = 0.f;
    if (tid < 32) x_sm[0][tid] = xin[tid];
    float c = 0.f;
    __syncthreads();

    for (int t = 0; t < TT; t++) {
        const int p = t & 1, np = p ^ 1;
        float xn = 0.f;
        if (tid < 32 && t + 1 < TT) xn = xin[(size_t)(t + 1) * 32 + tid];

        u64 a = pack2(bs, 0.f);
        {
            const ulonglong2* xv = (const ulonglong2*)&x_sm[p][0];
            #pragma unroll
            for (int q = 0; q < 8; q++) {
                ulonglong2 v = xv[q];
                a = ffma2(wi[2*q], v.x, a); a = ffma2(wi[2*q+1], v.y, a);
            }
            const ulonglong2* hv = (const ulonglong2*)&h_sm[p][0];
            #pragma unroll
            for (int q = 0; q < 16; q++) {
                ulonglong2 v = hv[q];
                a = ffma2(wh[2*q], v.x, a); a = ffma2(wh[2*q+1], v.y, a);
            }
        }
        g_sm[tid] = hsum2(a);
        __syncthreads();
        if (tid < 64) {
            float gi = g_sm[tid],       gf = g_sm[64 + tid];
            float gg = g_sm[128 + tid], go = g_sm[192 + tid];
            c = sigf(gf) * c + sigf(gi) * tanhf_(gg);
            float h = sigf(go) * tanhf_(c);
            h_sm[np][tid] = h;
            op[(size_t)t * 64 + tid] = h;
        }
        if (tid < 32) x_sm[np][tid] = xn;
        __syncthreads();
    }
}

// =======================================================================
// xg3 GEMM v2 + BIAS FOLD: 128-thread blocks (3 CTAs/SM). (passed R12)
// =======================================================================
__global__ void __launch_bounds__(128, 3) xg3_kernel(
    const float* __restrict__ w_ih,
    const float* __restrict__ b_ih, const float* __restrict__ b_hh)
{
    __shared__ __align__(16) float x_sm[64][64];   // 16 KB
    const int tid = threadIdx.x;
    const int b   = blockIdx.y;
    const int t0  = blockIdx.x * 64;
    const int r0  = blockIdx.z * 256 + tid;
    const int r1  = r0 + 128;

    u64 wa[32], wb[32];
    {
        const ulonglong2* wr = (const ulonglong2*)(w_ih + (size_t)r0 * 64);
        #pragma unroll
        for (int q = 0; q < 16; q++) { ulonglong2 v = wr[q]; wa[2*q] = v.x; wa[2*q+1] = v.y; }
        const ulonglong2* wr2 = (const ulonglong2*)(w_ih + (size_t)r1 * 64);
        #pragma unroll
        for (int q = 0; q < 16; q++) { ulonglong2 v = wr2[q]; wb[2*q] = v.x; wb[2*q+1] = v.y; }
    }
    const float bsA = b_ih[r0] + b_hh[r0];
    const float bsB = b_ih[r1] + b_hh[r1];
    {
        const float4* src = (const float4*)(g_h2 + (size_t)b * TT * 64 + (size_t)t0 * 64);
        float4* dst = (float4*)&x_sm[0][0];
        #pragma unroll
        for (int i = 0; i < 8; i++) dst[tid + 128 * i] = src[tid + 128 * i];
    }
    __syncthreads();

    float* outp = g_xg3 + ((size_t)b * TT + t0) * 512 + blockIdx.z * 256 + tid;
    for (int tk = 0; tk < 64; tk++) {
        const ulonglong2* xv = (const ulonglong2*)&x_sm[tk][0];
        u64 a0 = pack2(0.f, 0.f), a1 = a0;
        #pragma unroll
        for (int q = 0; q < 16; q++) {
            ulonglong2 v = xv[q];
            a0 = ffma2(wa[2*q], v.x, a0); a0 = ffma2(wa[2*q+1], v.y, a0);
            a1 = ffma2(wb[2*q], v.x, a1); a1 = ffma2(wb[2*q+1], v.y, a1);
        }
        outp[(size_t)tk * 512]       = hsum2(a0) + bsA;
        outp[(size_t)tk * 512 + 128] = hsum2(a1) + bsB;
    }
}

// =======================================================================
// Layer 3 v10: batch-pair software pipeline over the R4 proven core.
// 64 clusters x 2 CTAs, 4 batches/cluster, 512 threads/CTA, 1 CTA/SM.
// Even phase: FMA(pair A={b0,b1}, t)  ||  update(pair B, t-1)
// Odd  phase: FMA(pair B={b2,b3}, t)  ||  update(pair A, t)
// A-updaters = tid<128 (warps 0-3); B-updaters = tid 128..255 (warps 4-7):
// one updater warp per SMSP per phase, tail hidden under the other 12
// warps' FMA. psum[4][256][2] gate-major (conflict-free, disjoint rows per
// pair). Sync: cluster_sync per phase (2/step), all unconditional.
// =======================================================================
__global__ void __launch_bounds__(512, 1) __cluster_dims__(2, 1, 1) lstm3_kernel(
    const float* __restrict__ w_hh,
    const float* __restrict__ fc_w, const float* __restrict__ fc_b,
    float* __restrict__ out)
{
    __shared__ __align__(16) float h_sm[2][4][128];   // 4 KB [buf][batch][unit]
    __shared__ __align__(16) u64 psum[4][256][2];     // [batch][slot][half] 16 KB
    const int tid  = threadIdx.x;
    const unsigned rank = ctarank_();
    const int bg0  = (blockIdx.x >> 1) * 4;
    const int half = tid >> 8;            // warp-uniform K-half
    const int slot = tid & 255;
    const int gate = slot >> 6, jl = slot & 63;
    const int grow = gate * 128 + (int)rank * 64 + jl;

    u64 wh[32];
    {
        const ulonglong2* wr = (const ulonglong2*)(w_hh + (size_t)grow * 128 + half * 64);
        #pragma unroll
        for (int q = 0; q < 16; q++) { ulonglong2 v = wr[q]; wh[2*q] = v.x; wh[2*q+1] = v.y; }
    }

    // updater roles: tid<128 -> pair A (batches 0,1); tid 128..255 -> pair B (2,3)
    const bool updA = (tid < 128);
    const bool updB = (tid >= 128 && tid < 256);
    const int ub = (tid >> 6) & 3;        // 0,1 for A-upd; 2,3 for B-upd
    const int uj = tid & 63;
    const int ug = (int)rank * 64 + uj;
    const float* __restrict__ xgp =
        g_xg3 + ((size_t)(bg0 + ub) * TT) * 512 + ug;

    unsigned la0 = smem_u32(&h_sm[0][ub][ug]);
    unsigned la1 = smem_u32(&h_sm[1][ub][ug]);
    unsigned pa0 = mapa_u32(la0, rank ^ 1u);
    unsigned pa1 = mapa_u32(la1, rank ^ 1u);

    for (int i = tid; i < 4 * 128; i += 512) ((float*)h_sm[0])[i] = 0.f;
    float c = 0.f, hsumv = 0.f;
    float x0 = 0.f, x1 = 0.f, x2 = 0.f, x3 = 0.f;
    if (tid < 256) { x0 = xgp[0]; x1 = xgp[128]; x2 = xgp[256]; x3 = xgp[384]; }
    __syncthreads();
    cluster_sync_();

    for (int t = 0; t < TT; t++) {
        const int buf = t & 1;
        // ============ even phase: FMA(A, t) || update(B, t-1) ============
        {
            u64 a0 = pack2(0.f, 0.f), a1 = a0;
            const ulonglong2* hvb = (const ulonglong2*)&h_sm[buf][0][0] + half * 16;
            #pragma unroll
            for (int q = 0; q < 16; q++) {
                ulonglong2 v0 = hvb[q], v1 = hvb[32 + q];
                a0 = ffma2(wh[2*q], v0.x, a0); a0 = ffma2(wh[2*q+1], v0.y, a0);
                a1 = ffma2(wh[2*q], v1.x, a1); a1 = ffma2(wh[2*q+1], v1.y, a1);
            }
            psum[0][slot][half] = a0;
            psum[1][slot][half] = a1;
        }
        if (updB && t > 0) {
            // update pair B at time t-1 -> h(t) into h_sm[buf]
            const ulonglong2* ps = (const ulonglong2*)&psum[ub][0][0];
            ulonglong2 q0 = ps[0   + uj], q1 = ps[64  + uj];
            ulonglong2 q2 = ps[128 + uj], q3 = ps[192 + uj];
            float g0 = hsum2(q0.x) + hsum2(q0.y) + x0;
            float g1 = hsum2(q1.x) + hsum2(q1.y) + x1;
            float g2 = hsum2(q2.x) + hsum2(q2.y) + x2;
            float g3 = hsum2(q3.x) + hsum2(q3.y) + x3;
            c = sigf(g1) * c + sigf(g0) * tanhf_(g2);
            float h = sigf(g3) * tanhf_(c);
            hsumv += h;
            h_sm[buf][ub][ug] = h;
            st_cluster(buf ? pa1 : pa0, h);
            // prefetch xg(t) for next B update (consumed 2 phases later)
            const size_t o = (size_t)t * 512;
            x0 = xgp[o]; x1 = xgp[o + 128]; x2 = xgp[o + 256]; x3 = xgp[o + 384];
        }
        cluster_sync_();
        // ============ odd phase: FMA(B, t) || update(A, t) ============
        {
            u64 a2 = pack2(0.f, 0.f), a3 = a2;
            const ulonglong2* hvb = (const ulonglong2*)&h_sm[buf][2][0] + half * 16;
            #pragma unroll
            for (int q = 0; q < 16; q++) {
                ulonglong2 v2 = hvb[q], v3 = hvb[32 + q];
                a2 = ffma2(wh[2*q], v2.x, a2); a2 = ffma2(wh[2*q+1], v2.y, a2);
                a3 = ffma2(wh[2*q], v3.x, a3); a3 = ffma2(wh[2*q+1], v3.y, a3);
            }
            psum[2][slot][half] = a2;
            psum[3][slot][half] = a3;
        }
        if (updA) {
            // update pair A at time t -> h(t+1) into h_sm[buf^1]
            const ulonglong2* ps = (const ulonglong2*)&psum[ub][0][0];
            ulonglong2 q0 = ps[0   + uj], q1 = ps[64  + uj];
            ulonglong2 q2 = ps[128 + uj], q3 = ps[192 + uj];
            float g0 = hsum2(q0.x) + hsum2(q0.y) + x0;
            float g1 = hsum2(q1.x) + hsum2(q1.y) + x1;
            float g2 = hsum2(q2.x) + hsum2(q2.y) + x2;
            float g3 = hsum2(q3.x) + hsum2(q3.y) + x3;
            c = sigf(g1) * c + sigf(g0) * tanhf_(g2);
            float h = sigf(g3) * tanhf_(c);
            hsumv += h;
            h_sm[buf ^ 1][ub][ug] = h;
            st_cluster(buf ? pa0 : pa1, h);
            if (t + 1 < TT) {
                const size_t o = (size_t)(t + 1) * 512;
                x0 = xgp[o]; x1 = xgp[o + 128]; x2 = xgp[o + 256]; x3 = xgp[o + 384];
            }
        }
        cluster_sync_();
    }

    // drain: update pair B at t=1023 (hsum only; h(1024) unused)
    if (updB) {
        const ulonglong2* ps = (const ulonglong2*)&psum[ub][0][0];
        ulonglong2 q0 = ps[0   + uj], q1 = ps[64  + uj];
        ulonglong2 q2 = ps[128 + uj], q3 = ps[192 + uj];
        float g0 = hsum2(q0.x) + hsum2(q0.y) + x0;
        float g1 = hsum2(q1.x) + hsum2(q1.y) + x1;
        float g2 = hsum2(q2.x) + hsum2(q2.y) + x2;
        float g3 = hsum2(q3.x) + hsum2(q3.y) + x3;
        c = sigf(g1) * c + sigf(g0) * tanhf_(g2);
        hsumv += sigf(g3) * tanhf_(c);
    }
    cluster_sync_();

    // epilogue: pooled mean -> both CTAs' SMEM -> FC on rank 0
    if (tid < 256) {
        float pv = hsumv * (1.f / 1024.f);
        h_sm[0][ub][ug] = pv;
        st_cluster(pa0, pv);
    }
    cluster_sync_();
    if (rank == 0 && tid < 40) {
        const int b = tid / 10, m = tid % 10;
        float acc = fc_b[m];
        #pragma unroll 8
        for (int jj = 0; jj < 128; jj++)
            acc += h_sm[0][b][jj] * fc_w[m * 128 + jj];
        out[(size_t)(bg0 + b) * 10 + m] = acc;
    }
    cluster_sync_();   // keep SMEM alive until FC reads complete
}

// =======================================================================
extern "C" void kernel_launch(void* const* d_in, const int* in_sizes, int n_in,
                              void* d_out, int out_size)
{
    const float* x     = (const float*)d_in[0];
    const float* w_ih1 = (const float*)d_in[1];
    const float* w_hh1 = (const float*)d_in[2];
    const float* b_ih1 = (const float*)d_in[3];
    const float* b_hh1 = (const float*)d_in[4];
    const float* w_ih2 = (const float*)d_in[5];
    const float* w_hh2 = (const float*)d_in[6];
    const float* b_ih2 = (const float*)d_in[7];
    const float* b_hh2 = (const float*)d_in[8];
    const float* w_ih3 = (const float*)d_in[9];
    const float* w_hh3 = (const float*)d_in[10];
    const float* b_ih3 = (const float*)d_in[11];
    const float* b_hh3 = (const float*)d_in[12];
    const float* fc_w  = (const float*)d_in[13];
    const float* fc_b  = (const float*)d_in[14];
    float* out = (float*)d_out;

    lstm1_kernel<<<128, 64>>>(x, w_ih1, w_hh1, b_ih1, b_hh1);
    lstm2_kernel<<<256, 256>>>(w_ih2, w_hh2, b_ih2, b_hh2);
    {
        dim3 grid(TT / 64, 256, 2);
        xg3_kernel<<<grid, 128>>>(w_ih3, b_ih3, b_hh3);
    }
    lstm3_kernel<<<128, 512>>>(w_hh3, fc_w, fc_b, out);
}

// round 16
// speedup vs baseline: 1.1477x; 1.1477x over previous
#include <cuda_runtime.h>

#define TT 1024

// Inter-layer activations (device globals: allowed scratch)
__device__ float g_h2[256u * 1024u * 64u];        // layer2 output  (67 MB)
__device__ float g_xg3[(size_t)256 * 1024 * 512]; // layer3 input proj + bias (512 MB)

typedef unsigned long long u64;

// ---------------- packed f32x2 helpers ----------------
__device__ __forceinline__ u64 ffma2(u64 a, u64 b, u64 c) {
    u64 d;
    asm("fma.rn.f32x2 %0, %1, %2, %3;" : "=l"(d) : "l"(a), "l"(b), "l"(c));
    return d;
}
__device__ __forceinline__ u64 pack2(float x, float y) {
    u64 r;
    asm("mov.b64 %0, {%1, %2};" : "=l"(r) : "f"(x), "f"(y));
    return r;
}
__device__ __forceinline__ float hsum2(u64 v) {
    float x, y;
    asm("mov.b64 {%0, %1}, %2;" : "=f"(x), "=f"(y) : "l"(v));
    return x + y;
}
__device__ __forceinline__ void unpack2(u64 v, float& x, float& y) {
    asm("mov.b64 {%0, %1}, %2;" : "=f"(x), "=f"(y) : "l"(v));
}
// ---------------- activations (proven: rel_err 4e-7) --------
__device__ __forceinline__ float rcpa(float x) {
    float r; asm("rcp.approx.f32 %0, %1;" : "=f"(r) : "f"(x)); return r;
}
__device__ __forceinline__ float sigf(float x)   { return rcpa(1.f + __expf(-x)); }
__device__ __forceinline__ float tanhf_(float x) { return 1.f - 2.f * rcpa(__expf(2.f * x) + 1.f); }

// ---------------- cluster helpers (R4/R6-proven) ----------------
__device__ __forceinline__ unsigned smem_u32(const void* p) {
    return (unsigned)__cvta_generic_to_shared(p);
}
__device__ __forceinline__ unsigned mapa_u32(unsigned a, unsigned r) {
    unsigned o; asm("mapa.shared::cluster.u32 %0, %1, %2;" : "=r"(o) : "r"(a), "r"(r)); return o;
}
__device__ __forceinline__ void st_cluster(unsigned a, float v) {
    asm volatile("st.shared::cluster.f32 [%0], %1;" :: "r"(a), "f"(v) : "memory");
}
__device__ __forceinline__ void cluster_sync_() {
    asm volatile("barrier.cluster.arrive.aligned;" ::: "memory");
    asm volatile("barrier.cluster.wait.aligned;"   ::: "memory");
}
__device__ __forceinline__ unsigned ctarank_() {
    unsigned r; asm("mov.u32 %0, %%cluster_ctarank;" : "=r"(r)); return r;
}

// =======================================================================
// Fused layers 1+2: 256 CTAs (1 batch each) x 256 threads, 2 CTAs/SM.
// Warps 0-7: lstm2 gate rows (thread = row tid, 48 u64 weights in regs).
// During the update phase (tid<64 does the lstm2 update), warp 7 ALSO runs
// lstm1 (hid=32, lane=unit, weights in k-major SMEM) one step ahead,
// producing h1(t+1) into the double-buffered h1_sm that replaces x_sm.
// Sync per step: the same two __syncthreads as the proven lstm2.
// =======================================================================
__global__ void __launch_bounds__(256, 2) lstm12_kernel(
    const float* __restrict__ x,
    const float* __restrict__ w_ih1, const float* __restrict__ w_hh1,
    const float* __restrict__ b_ih1, const float* __restrict__ b_hh1,
    const float* __restrict__ w_ih2, const float* __restrict__ w_hh2,
    const float* __restrict__ b_ih2, const float* __restrict__ b_hh2)
{
    __shared__ __align__(16) float h_sm[2][64];     // lstm2 h, double-buffered
    __shared__ __align__(16) float h1_sm[2][32];    // lstm1 h (lstm2 input)
    __shared__ float g_sm[256];
    __shared__ __align__(8) u64 w1if_s[32][32];     // lstm1 (i,f) weights, k-major, 8KB
    __shared__ __align__(8) u64 w1go_s[32][32];     // lstm1 (g,o) weights, k-major, 8KB
    __shared__ __align__(8) u64 b1if_s[32], b1go_s[32], w1xi_s[32], w1xg_s[32];

    const int tid = threadIdx.x;
    const int b   = blockIdx.x;

    // ---- lstm2 per-thread weights (proven layout) ----
    u64 wh[32], wi[16];
    {
        const ulonglong2* wr = (const ulonglong2*)(w_hh2 + (size_t)tid * 64);
        #pragma unroll
        for (int q = 0; q < 16; q++) { ulonglong2 v = wr[q]; wh[2*q] = v.x; wh[2*q+1] = v.y; }
        const ulonglong2* wr2 = (const ulonglong2*)(w_ih2 + (size_t)tid * 32);
        #pragma unroll
        for (int q = 0; q < 8; q++)  { ulonglong2 v = wr2[q]; wi[2*q] = v.x; wi[2*q+1] = v.y; }
    }
    const float bs = b_ih2[tid] + b_hh2[tid];
    float* __restrict__ op = g_h2 + (size_t)b * TT * 64;

    // ---- lstm1 weights -> SMEM (k-major; all threads cooperate) ----
    for (int idx = tid; idx < 1024; idx += 256) {
        const int k = idx >> 5, j = idx & 31;
        w1if_s[k][j] = pack2(w_hh1[j * 32 + k],        w_hh1[(32 + j) * 32 + k]);
        w1go_s[k][j] = pack2(w_hh1[(64 + j) * 32 + k], w_hh1[(96 + j) * 32 + k]);
    }
    if (tid < 32) {
        const int j = tid;
        b1if_s[j] = pack2(b_ih1[j]      + b_hh1[j],      b_ih1[32 + j] + b_hh1[32 + j]);
        b1go_s[j] = pack2(b_ih1[64 + j] + b_hh1[64 + j], b_ih1[96 + j] + b_hh1[96 + j]);
        w1xi_s[j] = pack2(w_ih1[j],      w_ih1[32 + j]);
        w1xg_s[j] = pack2(w_ih1[64 + j], w_ih1[96 + j]);
    }
    if (tid < 64) h_sm[0][tid] = 0.f;
    __syncthreads();

    // ---- lstm1 state (warp 7 lanes) + prologue: compute h1(0) ----
    const bool w7 = (tid >= 224);
    const int  j1 = tid & 31;
    const float* __restrict__ xp = x + (size_t)b * TT;
    float h1 = 0.f, c1 = 0.f, xt = 0.f;
    if (w7) {
        // step 0: h1(0) from x(0), h=0 (recurrent term vanishes)
        float x0 = xp[0];
        u64 xtp = pack2(x0, x0);
        u64 aif = ffma2(w1xi_s[j1], xtp, b1if_s[j1]);
        u64 ago = ffma2(w1xg_s[j1], xtp, b1go_s[j1]);
        float gi, gf, gg, go;
        unpack2(aif, gi, gf); unpack2(ago, gg, go);
        c1 = sigf(gi) * tanhf_(gg);          // c(-1)=0
        h1 = sigf(go) * tanhf_(c1);
        h1_sm[0][j1] = h1;
        xt = xp[1];                           // x(1) for iter t=0
    }
    float c = 0.f;
    __syncthreads();

    for (int t = 0; t < TT; t++) {
        const int p = t & 1, np = p ^ 1;

        // -------- lstm2 FMA over h1(t) + h2(t) (all 256 threads) --------
        u64 a = pack2(bs, 0.f);
        {
            const ulonglong2* xv = (const ulonglong2*)&h1_sm[p][0];
            #pragma unroll
            for (int q = 0; q < 8; q++) {
                ulonglong2 v = xv[q];
                a = ffma2(wi[2*q], v.x, a); a = ffma2(wi[2*q+1], v.y, a);
            }
            const ulonglong2* hv = (const ulonglong2*)&h_sm[p][0];
            #pragma unroll
            for (int q = 0; q < 16; q++) {
                ulonglong2 v = hv[q];
                a = ffma2(wh[2*q], v.x, a); a = ffma2(wh[2*q+1], v.y, a);
            }
        }
        g_sm[tid] = hsum2(a);
        __syncthreads();

        // -------- update phase: lstm2 update (tid<64)  ||  lstm1 step (warp 7) ----
        if (tid < 64) {
            float gi = g_sm[tid],       gf = g_sm[64 + tid];
            float gg = g_sm[128 + tid], go = g_sm[192 + tid];
            c = sigf(gf) * c + sigf(gi) * tanhf_(gg);
            float h = sigf(go) * tanhf_(c);
            h_sm[np][tid] = h;
            op[(size_t)t * 64 + tid] = h;
        }
        if (w7 && t + 1 < TT) {
            // compute h1(t+1) from x(t+1) and h1(t) -> h1_sm[np]
            float xn = (t + 2 < TT) ? xp[t + 2] : 0.f;
            u64 xtp = pack2(xt, xt);
            u64 aif = ffma2(w1xi_s[j1], xtp, b1if_s[j1]);
            u64 ago = ffma2(w1xg_s[j1], xtp, b1go_s[j1]);
            #pragma unroll
            for (int k = 0; k < 32; k++) {
                float hk = __shfl_sync(0xffffffffu, h1, k);
                u64 hkp = pack2(hk, hk);
                aif = ffma2(w1if_s[k][j1], hkp, aif);
                ago = ffma2(w1go_s[k][j1], hkp, ago);
            }
            float gi, gf, gg, go;
            unpack2(aif, gi, gf); unpack2(ago, gg, go);
            c1 = sigf(gf) * c1 + sigf(gi) * tanhf_(gg);
            h1 = sigf(go) * tanhf_(c1);
            h1_sm[np][j1] = h1;
            xt = xn;
        }
        __syncthreads();
    }
}

// =======================================================================
// xg3 GEMM v2 + BIAS FOLD: 128-thread blocks (3 CTAs/SM). (passed R12)
// =======================================================================
__global__ void __launch_bounds__(128, 3) xg3_kernel(
    const float* __restrict__ w_ih,
    const float* __restrict__ b_ih, const float* __restrict__ b_hh)
{
    __shared__ __align__(16) float x_sm[64][64];   // 16 KB
    const int tid = threadIdx.x;
    const int b   = blockIdx.y;
    const int t0  = blockIdx.x * 64;
    const int r0  = blockIdx.z * 256 + tid;
    const int r1  = r0 + 128;

    u64 wa[32], wb[32];
    {
        const ulonglong2* wr = (const ulonglong2*)(w_ih + (size_t)r0 * 64);
        #pragma unroll
        for (int q = 0; q < 16; q++) { ulonglong2 v = wr[q]; wa[2*q] = v.x; wa[2*q+1] = v.y; }
        const ulonglong2* wr2 = (const ulonglong2*)(w_ih + (size_t)r1 * 64);
        #pragma unroll
        for (int q = 0; q < 16; q++) { ulonglong2 v = wr2[q]; wb[2*q] = v.x; wb[2*q+1] = v.y; }
    }
    const float bsA = b_ih[r0] + b_hh[r0];
    const float bsB = b_ih[r1] + b_hh[r1];
    {
        const float4* src = (const float4*)(g_h2 + (size_t)b * TT * 64 + (size_t)t0 * 64);
        float4* dst = (float4*)&x_sm[0][0];
        #pragma unroll
        for (int i = 0; i < 8; i++) dst[tid + 128 * i] = src[tid + 128 * i];
    }
    __syncthreads();

    float* outp = g_xg3 + ((size_t)b * TT + t0) * 512 + blockIdx.z * 256 + tid;
    for (int tk = 0; tk < 64; tk++) {
        const ulonglong2* xv = (const ulonglong2*)&x_sm[tk][0];
        u64 a0 = pack2(0.f, 0.f), a1 = a0;
        #pragma unroll
        for (int q = 0; q < 16; q++) {
            ulonglong2 v = xv[q];
            a0 = ffma2(wa[2*q], v.x, a0); a0 = ffma2(wa[2*q+1], v.y, a0);
            a1 = ffma2(wb[2*q], v.x, a1); a1 = ffma2(wb[2*q+1], v.y, a1);
        }
        outp[(size_t)tk * 512]       = hsum2(a0) + bsA;
        outp[(size_t)tk * 512 + 128] = hsum2(a1) + bsB;
    }
}

// =======================================================================
// Layer 3: EXACT R4/R12 proven structure (1.83 ms), bias folded in xg3.
// 64 clusters x 2 CTAs, 4 batches/cluster, 512 threads/CTA, 1 CTA/SM.
// Sync per step: __syncthreads (psum) + barrier.cluster (h) — the floor.
// =======================================================================
__global__ void __launch_bounds__(512, 1) __cluster_dims__(2, 1, 1) lstm3_kernel(
    const float* __restrict__ w_hh,
    const float* __restrict__ fc_w, const float* __restrict__ fc_b,
    float* __restrict__ out)
{
    __shared__ __align__(16) float h_sm[2][4][128];   // 4 KB
    __shared__ __align__(16) u64 psum[4][256][2];     // [batch][slot][half] 16 KB
    const int tid  = threadIdx.x;
    const unsigned rank = ctarank_();
    const int bg0  = (blockIdx.x >> 1) * 4;
    const int half = tid >> 8;            // warp-uniform K-half
    const int slot = tid & 255;
    const int gate = slot >> 6, jl = slot & 63;
    const int grow = gate * 128 + (int)rank * 64 + jl;

    u64 wh[32];
    {
        const ulonglong2* wr = (const ulonglong2*)(w_hh + (size_t)grow * 128 + half * 64);
        #pragma unroll
        for (int q = 0; q < 16; q++) { ulonglong2 v = wr[q]; wh[2*q] = v.x; wh[2*q+1] = v.y; }
    }

    const bool upd = (tid < 256);
    const int ub = (tid >> 6) & 3, uj = tid & 63;
    const float* __restrict__ xgp =
        g_xg3 + ((size_t)(bg0 + ub) * TT) * 512 + (size_t)rank * 64 + uj;

    unsigned la0 = smem_u32(&h_sm[0][ub][(int)rank * 64 + uj]);
    unsigned la1 = smem_u32(&h_sm[1][ub][(int)rank * 64 + uj]);
    unsigned pa0 = mapa_u32(la0, rank ^ 1u);
    unsigned pa1 = mapa_u32(la1, rank ^ 1u);

    for (int i = tid; i < 4 * 128; i += 512) ((float*)h_sm[0])[i] = 0.f;
    float c = 0.f, hsum = 0.f;
    float x0 = 0.f, x1 = 0.f, x2 = 0.f, x3 = 0.f;
    if (upd) { x0 = xgp[0]; x1 = xgp[128]; x2 = xgp[256]; x3 = xgp[384]; }
    __syncthreads();
    cluster_sync_();

    for (int t = 0; t < TT; t++) {
        const int p = t & 1;
        float n0 = 0.f, n1 = 0.f, n2 = 0.f, n3 = 0.f;
        if (upd && t + 1 < TT) {
            const size_t o = (size_t)(t + 1) * 512;
            n0 = xgp[o]; n1 = xgp[o + 128]; n2 = xgp[o + 256]; n3 = xgp[o + 384];
        }

        u64 a0 = pack2(0.f, 0.f), a1 = a0, a2 = a0, a3 = a0;
        {
            const ulonglong2* hvb = (const ulonglong2*)&h_sm[p][0][0] + half * 16;
            #pragma unroll
            for (int q = 0; q < 16; q++) {
                ulonglong2 v0 = hvb[q], v1 = hvb[32 + q], v2 = hvb[64 + q], v3 = hvb[96 + q];
                a0 = ffma2(wh[2*q], v0.x, a0); a0 = ffma2(wh[2*q+1], v0.y, a0);
                a1 = ffma2(wh[2*q], v1.x, a1); a1 = ffma2(wh[2*q+1], v1.y, a1);
                a2 = ffma2(wh[2*q], v2.x, a2); a2 = ffma2(wh[2*q+1], v2.y, a2);
                a3 = ffma2(wh[2*q], v3.x, a3); a3 = ffma2(wh[2*q+1], v3.y, a3);
            }
        }
        psum[0][slot][half] = a0;
        psum[1][slot][half] = a1;
        psum[2][slot][half] = a2;
        psum[3][slot][half] = a3;
        __syncthreads();

        if (upd) {
            const ulonglong2* ps = (const ulonglong2*)&psum[ub][0][0];
            ulonglong2 q0 = ps[0   + uj], q1 = ps[64  + uj];
            ulonglong2 q2 = ps[128 + uj], q3 = ps[192 + uj];
            float g0 = hsum2(q0.x) + hsum2(q0.y) + x0;
            float g1 = hsum2(q1.x) + hsum2(q1.y) + x1;
            float g2 = hsum2(q2.x) + hsum2(q2.y) + x2;
            float g3 = hsum2(q3.x) + hsum2(q3.y) + x3;
            c = sigf(g1) * c + sigf(g0) * tanhf_(g2);
            float h = sigf(g3) * tanhf_(c);
            hsum += h;
            if (p == 0) { h_sm[1][ub][(int)rank * 64 + uj] = h; st_cluster(pa1, h); }
            else        { h_sm[0][ub][(int)rank * 64 + uj] = h; st_cluster(pa0, h); }
            x0 = n0; x1 = n1; x2 = n2; x3 = n3;
        }
        cluster_sync_();
    }

    // epilogue: pooled mean -> both CTAs' SMEM -> FC on rank 0
    if (upd) {
        float pv = hsum * (1.f / 1024.f);
        h_sm[0][ub][(int)rank * 64 + uj] = pv;
        st_cluster(pa0, pv);
    }
    cluster_sync_();
    if (rank == 0 && tid < 40) {
        const int b = tid / 10, m = tid % 10;
        float acc = fc_b[m];
        #pragma unroll 8
        for (int jj = 0; jj < 128; jj++)
            acc += h_sm[0][b][jj] * fc_w[m * 128 + jj];
        out[(size_t)(bg0 + b) * 10 + m] = acc;
    }
    cluster_sync_();   // keep SMEM alive until FC reads complete
}

// =======================================================================
extern "C" void kernel_launch(void* const* d_in, const int* in_sizes, int n_in,
                              void* d_out, int out_size)
{
    const float* x     = (const float*)d_in[0];
    const float* w_ih1 = (const float*)d_in[1];
    const float* w_hh1 = (const float*)d_in[2];
    const float* b_ih1 = (const float*)d_in[3];
    const float* b_hh1 = (const float*)d_in[4];
    const float* w_ih2 = (const float*)d_in[5];
    const float* w_hh2 = (const float*)d_in[6];
    const float* b_ih2 = (const float*)d_in[7];
    const float* b_hh2 = (const float*)d_in[8];
    const float* w_ih3 = (const float*)d_in[9];
    const float* w_hh3 = (const float*)d_in[10];
    const float* b_ih3 = (const float*)d_in[11];
    const float* b_hh3 = (const float*)d_in[12];
    const float* fc_w  = (const float*)d_in[13];
    const float* fc_b  = (const float*)d_in[14];
    float* out = (float*)d_out;

    lstm12_kernel<<<256, 256>>>(x, w_ih1, w_hh1, b_ih1, b_hh1,
                                w_ih2, w_hh2, b_ih2, b_hh2);
    {
        dim3 grid(TT / 64, 256, 2);
        xg3_kernel<<<grid, 128>>>(w_ih3, b_ih3, b_hh3);
    }
    lstm3_kernel<<<128, 512>>>(w_hh3, fc_w, fc_b, out);
}

// round 17
// speedup vs baseline: 1.4180x; 1.2355x over previous
#include <cuda_runtime.h>

#define TT 1024

// Inter-layer activations (device globals: allowed scratch)
__device__ float g_h1[256u * 1024u * 32u];        // layer1 output  (33.5 MB)
__device__ float g_h2[256u * 1024u * 64u];        // layer2 output  (67 MB)
__device__ float g_xg3[(size_t)256 * 1024 * 512]; // layer3 input proj + bias (512 MB)

typedef unsigned long long u64;

// ---------------- packed f32x2 helpers ----------------
__device__ __forceinline__ u64 ffma2(u64 a, u64 b, u64 c) {
    u64 d;
    asm("fma.rn.f32x2 %0, %1, %2, %3;" : "=l"(d) : "l"(a), "l"(b), "l"(c));
    return d;
}
__device__ __forceinline__ u64 pack2(float x, float y) {
    u64 r;
    asm("mov.b64 %0, {%1, %2};" : "=l"(r) : "f"(x), "f"(y));
    return r;
}
__device__ __forceinline__ float hsum2(u64 v) {
    float x, y;
    asm("mov.b64 {%0, %1}, %2;" : "=f"(x), "=f"(y) : "l"(v));
    return x + y;
}
__device__ __forceinline__ void unpack2(u64 v, float& x, float& y) {
    asm("mov.b64 {%0, %1}, %2;" : "=f"(x), "=f"(y) : "l"(v));
}
// ---------------- activations (proven: rel_err 4e-7) --------
__device__ __forceinline__ float rcpa(float x) {
    float r; asm("rcp.approx.f32 %0, %1;" : "=f"(r) : "f"(x)); return r;
}
__device__ __forceinline__ float sigf(float x)   { return rcpa(1.f + __expf(-x)); }
__device__ __forceinline__ float tanhf_(float x) { return 1.f - 2.f * rcpa(__expf(2.f * x) + 1.f); }

// ---------------- cluster helpers (R4/R6-proven) ----------------
__device__ __forceinline__ unsigned smem_u32(const void* p) {
    return (unsigned)__cvta_generic_to_shared(p);
}
__device__ __forceinline__ unsigned mapa_u32(unsigned a, unsigned r) {
    unsigned o; asm("mapa.shared::cluster.u32 %0, %1, %2;" : "=r"(o) : "r"(a), "r"(r)); return o;
}
__device__ __forceinline__ void st_cluster(unsigned a, float v) {
    asm volatile("st.shared::cluster.f32 [%0], %1;" :: "r"(a), "f"(v) : "memory");
}
__device__ __forceinline__ void cluster_sync_() {
    asm volatile("barrier.cluster.arrive.aligned;" ::: "memory");
    asm volatile("barrier.cluster.wait.aligned;"   ::: "memory");
}
__device__ __forceinline__ unsigned ctarank_() {
    unsigned r; asm("mov.u32 %0, %%cluster_ctarank;" : "=r"(r)); return r;
}

// =======================================================================
// Layer 1 v2: in=1, hid=32.  One WARP per batch; zero barriers.
// 4 accumulator chains. 128 blocks x 64 threads. (passed R12 @ 3188)
// =======================================================================
__global__ void __launch_bounds__(64, 1) lstm1_kernel(
    const float* __restrict__ x,    const float* __restrict__ w_ih,
    const float* __restrict__ w_hh, const float* __restrict__ b_ih,
    const float* __restrict__ b_hh)
{
    const int tid = threadIdx.x;
    const int j   = tid & 31;
    const int b   = blockIdx.x * 2 + (tid >> 5);

    u64 wif[32], wgo[32];
    #pragma unroll
    for (int k = 0; k < 32; k++) {
        wif[k] = pack2(w_hh[(0  + j) * 32 + k], w_hh[(32 + j) * 32 + k]);
        wgo[k] = pack2(w_hh[(64 + j) * 32 + k], w_hh[(96 + j) * 32 + k]);
    }
    const u64 bif  = pack2(b_ih[j]      + b_hh[j],      b_ih[32 + j] + b_hh[32 + j]);
    const u64 bgo  = pack2(b_ih[64 + j] + b_hh[64 + j], b_ih[96 + j] + b_hh[96 + j]);
    const u64 wiif = pack2(w_ih[j],      w_ih[32 + j]);
    const u64 wigo = pack2(w_ih[64 + j], w_ih[96 + j]);

    const float* __restrict__ xp = x + (size_t)b * TT;
    float* __restrict__ op = g_h1 + (size_t)b * TT * 32 + j;
    float h = 0.f, c = 0.f;
    float xt = xp[0];

    for (int t = 0; t < TT; t++) {
        float xn = (t + 1 < TT) ? xp[t + 1] : 0.f;
        u64 xtp = pack2(xt, xt);
        u64 aif0 = ffma2(wiif, xtp, bif);
        u64 ago0 = ffma2(wigo, xtp, bgo);
        u64 aif1 = pack2(0.f, 0.f), ago1 = aif1;
        #pragma unroll
        for (int k = 0; k < 16; k++) {
            float hk  = __shfl_sync(0xffffffffu, h, k);
            float hk2 = __shfl_sync(0xffffffffu, h, k + 16);
            u64 hp  = pack2(hk,  hk);
            u64 hp2 = pack2(hk2, hk2);
            aif0 = ffma2(wif[k],      hp,  aif0);
            ago0 = ffma2(wgo[k],      hp,  ago0);
            aif1 = ffma2(wif[k + 16], hp2, aif1);
            ago1 = ffma2(wgo[k + 16], hp2, ago1);
        }
        float i0, f0, i1, f1, g0, o0, g1, o1;
        unpack2(aif0, i0, f0); unpack2(aif1, i1, f1);
        unpack2(ago0, g0, o0); unpack2(ago1, g1, o1);
        float gi = i0 + i1, gf = f0 + f1, gg = g0 + g1, go = o0 + o1;
        c = sigf(gf) * c + sigf(gi) * tanhf_(gg);
        h = sigf(go) * tanhf_(c);
        op[(size_t)t * 32] = h;
        xt = xn;
    }
}

// =======================================================================
// Layer 2: in=32, hid=64.  ONE batch per CTA, 256 CTAs x 256 threads.
// (R6/R12 proven version: updater tid<64, g_sm round trip)
// =======================================================================
__global__ void __launch_bounds__(256, 2) lstm2_kernel(
    const float* __restrict__ w_ih, const float* __restrict__ w_hh,
    const float* __restrict__ b_ih, const float* __restrict__ b_hh)
{
    __shared__ __align__(16) float h_sm[2][64];
    __shared__ __align__(16) float x_sm[2][32];
    __shared__ float g_sm[256];
    const int tid = threadIdx.x;
    const int b   = blockIdx.x;

    u64 wh[32], wi[16];
    {
        const ulonglong2* wr = (const ulonglong2*)(w_hh + (size_t)tid * 64);
        #pragma unroll
        for (int q = 0; q < 16; q++) { ulonglong2 v = wr[q]; wh[2*q] = v.x; wh[2*q+1] = v.y; }
        const ulonglong2* wr2 = (const ulonglong2*)(w_ih + (size_t)tid * 32);
        #pragma unroll
        for (int q = 0; q < 8; q++)  { ulonglong2 v = wr2[q]; wi[2*q] = v.x; wi[2*q+1] = v.y; }
    }
    const float bs = b_ih[tid] + b_hh[tid];
    const float* __restrict__ xin = g_h1 + (size_t)b * TT * 32;
    float* __restrict__ op = g_h2 + (size_t)b * TT * 64;

    if (tid < 64) h_sm[0][tid] = 0.f;
    if (tid < 32) x_sm[0][tid] = xin[tid];
    float c = 0.f;
    __syncthreads();

    for (int t = 0; t < TT; t++) {
        const int p = t & 1, np = p ^ 1;
        float xn = 0.f;
        if (tid < 32 && t + 1 < TT) xn = xin[(size_t)(t + 1) * 32 + tid];

        u64 a = pack2(bs, 0.f);
        {
            const ulonglong2* xv = (const ulonglong2*)&x_sm[p][0];
            #pragma unroll
            for (int q = 0; q < 8; q++) {
                ulonglong2 v = xv[q];
                a = ffma2(wi[2*q], v.x, a); a = ffma2(wi[2*q+1], v.y, a);
            }
            const ulonglong2* hv = (const ulonglong2*)&h_sm[p][0];
            #pragma unroll
            for (int q = 0; q < 16; q++) {
                ulonglong2 v = hv[q];
                a = ffma2(wh[2*q], v.x, a); a = ffma2(wh[2*q+1], v.y, a);
            }
        }
        g_sm[tid] = hsum2(a);
        __syncthreads();
        if (tid < 64) {
            float gi = g_sm[tid],       gf = g_sm[64 + tid];
            float gg = g_sm[128 + tid], go = g_sm[192 + tid];
            c = sigf(gf) * c + sigf(gi) * tanhf_(gg);
            float h = sigf(go) * tanhf_(c);
            h_sm[np][tid] = h;
            op[(size_t)t * 64 + tid] = h;
        }
        if (tid < 32) x_sm[np][tid] = xn;
        __syncthreads();
    }
}

// =======================================================================
// xg3 GEMM v3 + BIAS FOLD: 128-thread blocks (3 CTAs/SM), 4 accumulator
// chains (depth 16 instead of 32) to unexpose the LDS->FFMA latency.
// xg3[b][t][g] = sum_k h2[b][t][k]*w_ih3[g][k] + bias[g]
// =======================================================================
__global__ void __launch_bounds__(128, 3) xg3_kernel(
    const float* __restrict__ w_ih,
    const float* __restrict__ b_ih, const float* __restrict__ b_hh)
{
    __shared__ __align__(16) float x_sm[64][64];   // 16 KB
    const int tid = threadIdx.x;
    const int b   = blockIdx.y;
    const int t0  = blockIdx.x * 64;
    const int r0  = blockIdx.z * 256 + tid;
    const int r1  = r0 + 128;

    u64 wa[32], wb[32];
    {
        const ulonglong2* wr = (const ulonglong2*)(w_ih + (size_t)r0 * 64);
        #pragma unroll
        for (int q = 0; q < 16; q++) { ulonglong2 v = wr[q]; wa[2*q] = v.x; wa[2*q+1] = v.y; }
        const ulonglong2* wr2 = (const ulonglong2*)(w_ih + (size_t)r1 * 64);
        #pragma unroll
        for (int q = 0; q < 16; q++) { ulonglong2 v = wr2[q]; wb[2*q] = v.x; wb[2*q+1] = v.y; }
    }
    const float bsA = b_ih[r0] + b_hh[r0];
    const float bsB = b_ih[r1] + b_hh[r1];
    {
        const float4* src = (const float4*)(g_h2 + (size_t)b * TT * 64 + (size_t)t0 * 64);
        float4* dst = (float4*)&x_sm[0][0];
        #pragma unroll
        for (int i = 0; i < 8; i++) dst[tid + 128 * i] = src[tid + 128 * i];
    }
    __syncthreads();

    float* outp = g_xg3 + ((size_t)b * TT + t0) * 512 + blockIdx.z * 256 + tid;
    for (int tk = 0; tk < 64; tk++) {
        const ulonglong2* xv = (const ulonglong2*)&x_sm[tk][0];
        // 4 independent chains: (row0 lo/hi), (row1 lo/hi) -> depth 16 each
        u64 a0a = pack2(0.f, 0.f), a0b = a0a, a1a = a0a, a1b = a0a;
        #pragma unroll
        for (int q = 0; q < 8; q++) {
            ulonglong2 vlo = xv[q], vhi = xv[8 + q];
            a0a = ffma2(wa[2*q],      vlo.x, a0a); a0a = ffma2(wa[2*q+1],      vlo.y, a0a);
            a0b = ffma2(wa[16+2*q],   vhi.x, a0b); a0b = ffma2(wa[16+2*q+1],   vhi.y, a0b);
            a1a = ffma2(wb[2*q],      vlo.x, a1a); a1a = ffma2(wb[2*q+1],      vlo.y, a1a);
            a1b = ffma2(wb[16+2*q],   vhi.x, a1b); a1b = ffma2(wb[16+2*q+1],   vhi.y, a1b);
        }
        outp[(size_t)tk * 512]       = hsum2(a0a) + hsum2(a0b) + bsA;
        outp[(size_t)tk * 512 + 128] = hsum2(a1a) + hsum2(a1b) + bsB;
    }
}

// =======================================================================
// Layer 3: EXACT R4/R12 proven structure (1.83 ms), bias folded in xg3.
// 64 clusters x 2 CTAs, 4 batches/cluster, 512 threads/CTA, 1 CTA/SM.
// Sync per step: __syncthreads (psum) + barrier.cluster (h) — the floor.
// =======================================================================
__global__ void __launch_bounds__(512, 1) __cluster_dims__(2, 1, 1) lstm3_kernel(
    const float* __restrict__ w_hh,
    const float* __restrict__ fc_w, const float* __restrict__ fc_b,
    float* __restrict__ out)
{
    __shared__ __align__(16) float h_sm[2][4][128];   // 4 KB
    __shared__ __align__(16) u64 psum[4][256][2];     // [batch][slot][half] 16 KB
    const int tid  = threadIdx.x;
    const unsigned rank = ctarank_();
    const int bg0  = (blockIdx.x >> 1) * 4;
    const int half = tid >> 8;            // warp-uniform K-half
    const int slot = tid & 255;
    const int gate = slot >> 6, jl = slot & 63;
    const int grow = gate * 128 + (int)rank * 64 + jl;

    u64 wh[32];
    {
        const ulonglong2* wr = (const ulonglong2*)(w_hh + (size_t)grow * 128 + half * 64);
        #pragma unroll
        for (int q = 0; q < 16; q++) { ulonglong2 v = wr[q]; wh[2*q] = v.x; wh[2*q+1] = v.y; }
    }

    const bool upd = (tid < 256);
    const int ub = (tid >> 6) & 3, uj = tid & 63;
    const float* __restrict__ xgp =
        g_xg3 + ((size_t)(bg0 + ub) * TT) * 512 + (size_t)rank * 64 + uj;

    unsigned la0 = smem_u32(&h_sm[0][ub][(int)rank * 64 + uj]);
    unsigned la1 = smem_u32(&h_sm[1][ub][(int)rank * 64 + uj]);
    unsigned pa0 = mapa_u32(la0, rank ^ 1u);
    unsigned pa1 = mapa_u32(la1, rank ^ 1u);

    for (int i = tid; i < 4 * 128; i += 512) ((float*)h_sm[0])[i] = 0.f;
    float c = 0.f, hsum = 0.f;
    float x0 = 0.f, x1 = 0.f, x2 = 0.f, x3 = 0.f;
    if (upd) { x0 = xgp[0]; x1 = xgp[128]; x2 = xgp[256]; x3 = xgp[384]; }
    __syncthreads();
    cluster_sync_();

    for (int t = 0; t < TT; t++) {
        const int p = t & 1;
        float n0 = 0.f, n1 = 0.f, n2 = 0.f, n3 = 0.f;
        if (upd && t + 1 < TT) {
            const size_t o = (size_t)(t + 1) * 512;
            n0 = xgp[o]; n1 = xgp[o + 128]; n2 = xgp[o + 256]; n3 = xgp[o + 384];
        }

        u64 a0 = pack2(0.f, 0.f), a1 = a0, a2 = a0, a3 = a0;
        {
            const ulonglong2* hvb = (const ulonglong2*)&h_sm[p][0][0] + half * 16;
            #pragma unroll
            for (int q = 0; q < 16; q++) {
                ulonglong2 v0 = hvb[q], v1 = hvb[32 + q], v2 = hvb[64 + q], v3 = hvb[96 + q];
                a0 = ffma2(wh[2*q], v0.x, a0); a0 = ffma2(wh[2*q+1], v0.y, a0);
                a1 = ffma2(wh[2*q], v1.x, a1); a1 = ffma2(wh[2*q+1], v1.y, a1);
                a2 = ffma2(wh[2*q], v2.x, a2); a2 = ffma2(wh[2*q+1], v2.y, a2);
                a3 = ffma2(wh[2*q], v3.x, a3); a3 = ffma2(wh[2*q+1], v3.y, a3);
            }
        }
        psum[0][slot][half] = a0;
        psum[1][slot][half] = a1;
        psum[2][slot][half] = a2;
        psum[3][slot][half] = a3;
        __syncthreads();

        if (upd) {
            const ulonglong2* ps = (const ulonglong2*)&psum[ub][0][0];
            ulonglong2 q0 = ps[0   + uj], q1 = ps[64  + uj];
            ulonglong2 q2 = ps[128 + uj], q3 = ps[192 + uj];
            float g0 = hsum2(q0.x) + hsum2(q0.y) + x0;
            float g1 = hsum2(q1.x) + hsum2(q1.y) + x1;
            float g2 = hsum2(q2.x) + hsum2(q2.y) + x2;
            float g3 = hsum2(q3.x) + hsum2(q3.y) + x3;
            c = sigf(g1) * c + sigf(g0) * tanhf_(g2);
            float h = sigf(g3) * tanhf_(c);
            hsum += h;
            if (p == 0) { h_sm[1][ub][(int)rank * 64 + uj] = h; st_cluster(pa1, h); }
            else        { h_sm[0][ub][(int)rank * 64 + uj] = h; st_cluster(pa0, h); }
            x0 = n0; x1 = n1; x2 = n2; x3 = n3;
        }
        cluster_sync_();
    }

    // epilogue: pooled mean -> both CTAs' SMEM -> FC on rank 0
    if (upd) {
        float pv = hsum * (1.f / 1024.f);
        h_sm[0][ub][(int)rank * 64 + uj] = pv;
        st_cluster(pa0, pv);
    }
    cluster_sync_();
    if (rank == 0 && tid < 40) {
        const int b = tid / 10, m = tid % 10;
        float acc = fc_b[m];
        #pragma unroll 8
        for (int jj = 0; jj < 128; jj++)
            acc += h_sm[0][b][jj] * fc_w[m * 128 + jj];
        out[(size_t)(bg0 + b) * 10 + m] = acc;
    }
    cluster_sync_();   // keep SMEM alive until FC reads complete
}

// =======================================================================
extern "C" void kernel_launch(void* const* d_in, const int* in_sizes, int n_in,
                              void* d_out, int out_size)
{
    const float* x     = (const float*)d_in[0];
    const float* w_ih1 = (const float*)d_in[1];
    const float* w_hh1 = (const float*)d_in[2];
    const float* b_ih1 = (const float*)d_in[3];
    const float* b_hh1 = (const float*)d_in[4];
    const float* w_ih2 = (const float*)d_in[5];
    const float* w_hh2 = (const float*)d_in[6];
    const float* b_ih2 = (const float*)d_in[7];
    const float* b_hh2 = (const float*)d_in[8];
    const float* w_ih3 = (const float*)d_in[9];
    const float* w_hh3 = (const float*)d_in[10];
    const float* b_ih3 = (const float*)d_in[11];
    const float* b_hh3 = (const float*)d_in[12];
    const float* fc_w  = (const float*)d_in[13];
    const float* fc_b  = (const float*)d_in[14];
    float* out = (float*)d_out;

    lstm1_kernel<<<128, 64>>>(x, w_ih1, w_hh1, b_ih1, b_hh1);
    lstm2_kernel<<<256, 256>>>(w_ih2, w_hh2, b_ih2, b_hh2);
    {
        dim3 grid(TT / 64, 256, 2);
        xg3_kernel<<<grid, 128>>>(w_ih3, b_ih3, b_hh3);
    }
    lstm3_kernel<<<128, 512>>>(w_hh3, fc_w, fc_b, out);
}